// round 16
// baseline (speedup 1.0000x reference)
#include <cuda_runtime.h>
#include <math_constants.h>

#define BATCH   32
#define LCACHE  8192
#define NKV     4
#define NH      16
#define HD      128
#define HID     2048
#define QKVW    3072          // 2048 q + 512 k + 512 v
#define GROUPS  4             // NH / NKV
#define NSPLIT  32
#define SPLIT_LEN 256         // LCACHE / NSPLIT
#define KSPLIT  8             // k-split for the two GEMMs (256 k per CTA)
#define AW      4             // warps per attn CTA
#define TILE    8             // positions per tile (2 per warp)
#define NSTG    4             // per-warp cp.async ring stages
#define NT      (SPLIT_LEN / TILE)   // 32 tiles per CTA

// scale * log2(e) : (1/sqrt(128)) * 1.4426950408889634
#define SCLOG2E (1.4426950408889634f * 0.08838834764831845f)
// fixed softmax bias in log2 space (validated R5/R7/R10-R15): pw = 2^(s-20)
#define MBIAS   20.0f
#define FULLM   0xffffffffu

__device__ __forceinline__ float ex2(float x) {
    float y; asm("ex2.approx.ftz.f32 %0, %1;" : "=f"(y) : "f"(x)); return y;
}
__device__ __forceinline__ void cp16(void* smem, const void* gmem) {
    unsigned sa = (unsigned)__cvta_generic_to_shared(smem);
    asm volatile("cp.async.cg.shared.global [%0], [%1], 16;" :: "r"(sa), "l"(gmem));
}
__device__ __forceinline__ void cp_commit() {
    asm volatile("cp.async.commit_group;");
}
__device__ __forceinline__ void cp_wait2() {
    asm volatile("cp.async.wait_group 2;");
}
__device__ __forceinline__ void cp_wait0() {
    asm volatile("cp.async.wait_group 0;");
}

// ---------------- scratch (device globals) ---------------------------------
__device__ float g_qkv_part[KSPLIT][BATCH][QKVW];     // 3.15 MB
__device__ float g_qn[BATCH][NH][HD];
__device__ float g_kn[BATCH][NKV][HD];
__device__ float g_vn[BATCH][NKV][HD];
__device__ float g_pacc[BATCH * NKV][NSPLIT][GROUPS][HD];
__device__ float g_pl[BATCH * NKV][NSPLIT][GROUPS];
__device__ float g_attn[BATCH][HID];
__device__ float g_opart[KSPLIT][BATCH][HID];         // 2.1 MB

// ---------------- 1) QKV GEMM (256 k per CTA, two smem passes) -------------
__global__ void qkv_gemm_k(const float* __restrict__ hidden,
                           const float* __restrict__ w) {
    const int nblk = blockIdx.x;   // 0..23
    const int ks   = blockIdx.y;   // 0..7
    const int tid  = threadIdx.x;  // 128

    __shared__ float hs[BATCH][128];
    const int n = nblk * 128 + tid;
    float acc[BATCH];
#pragma unroll
    for (int b = 0; b < BATCH; b++) acc[b] = 0.f;

#pragma unroll
    for (int c = 0; c < 2; c++) {
        const int k0 = ks * 256 + c * 128;
        __syncthreads();
        for (int i = tid; i < BATCH * 128; i += 128) {
            int b = i >> 7, kk = i & 127;
            hs[b][kk] = hidden[b * HID + k0 + kk];
        }
        __syncthreads();

        const float* wp = w + (size_t)k0 * QKVW + n;
#pragma unroll 2
        for (int kk4 = 0; kk4 < 32; kk4++) {
            float w0 = __ldg(wp + (size_t)(kk4 * 4 + 0) * QKVW);
            float w1 = __ldg(wp + (size_t)(kk4 * 4 + 1) * QKVW);
            float w2 = __ldg(wp + (size_t)(kk4 * 4 + 2) * QKVW);
            float w3 = __ldg(wp + (size_t)(kk4 * 4 + 3) * QKVW);
#pragma unroll
            for (int b = 0; b < BATCH; b++) {
                float4 h4 = *(const float4*)&hs[b][kk4 * 4];
                acc[b] = fmaf(h4.x, w0, fmaf(h4.y, w1, fmaf(h4.z, w2, fmaf(h4.w, w3, acc[b]))));
            }
        }
    }
#pragma unroll
    for (int b = 0; b < BATCH; b++) g_qkv_part[ks][b][n] = acc[b];
}

// ---------------- 2) sum partials + bias + per-head RMSNorm ----------------
__global__ void rmsnorm_k(const float* __restrict__ b_qkv,
                          const float* __restrict__ q_gamma,
                          const float* __restrict__ k_gamma) {
    const int seg = blockIdx.x;
    const int b   = blockIdx.y;
    const int tid = threadIdx.x;
    const int col = seg * 128 + tid;

    float v = b_qkv[col];
#pragma unroll
    for (int s = 0; s < KSPLIT; s++) v += g_qkv_part[s][b][col];

    if (seg < 20) {
        float ss = v * v;
#pragma unroll
        for (int o = 16; o; o >>= 1) ss += __shfl_xor_sync(FULLM, ss, o);
        __shared__ float wsum[4];
        if ((tid & 31) == 0) wsum[tid >> 5] = ss;
        __syncthreads();
        float tot = wsum[0] + wsum[1] + wsum[2] + wsum[3];
        float r = rsqrtf(tot * (1.f / 128.f) + 1e-6f);
        if (seg < 16) g_qn[b][seg][tid]      = v * r * q_gamma[tid];
        else          g_kn[b][seg - 16][tid] = v * r * k_gamma[tid];
    } else {
        g_vn[b][seg - 20][tid] = v;
    }
}

// ---------------- 3) flash-decode: R12-exact body, warp-private rings ------
__global__ void __launch_bounds__(128, 6)
attn_k(const float* __restrict__ k_cache, const float* __restrict__ v_cache) {
    const int split = blockIdx.x;
    const int pair  = blockIdx.y;
    const int b     = pair >> 2;
    const int kv    = pair & 3;
    const int tid   = threadIdx.x;
    const int warp  = tid >> 5;
    const int lane  = tid & 31;

    // per-warp private rings: each lane reads back exactly the 16B segment
    // it copied -> per-thread wait_group suffices, no CTA barrier.
    __shared__ __align__(16) float kring[AW][NSTG][2][HD];  // 16 KB
    __shared__ __align__(16) float vring[AW][NSTG][2][HD];  // 16 KB
    __shared__ float qs[GROUPS][HD];                        // 2 KB
    __shared__ float s_l[AW][GROUPS];

    // q scaled by scale*log2e, then kept in registers
    for (int i = tid; i < GROUPS * HD; i += 128)
        qs[i >> 7][i & 127] = g_qn[b][kv * GROUPS + (i >> 7)][i & 127] * SCLOG2E;
    __syncthreads();

    float qf[GROUPS][4];
#pragma unroll
    for (int h = 0; h < GROUPS; h++) {
        float4 q4 = *(const float4*)&qs[h][lane * 4];
        qf[h][0] = q4.x; qf[h][1] = q4.y; qf[h][2] = q4.z; qf[h][3] = q4.w;
    }

    float l[GROUPS], acc[GROUPS][4];
#pragma unroll
    for (int h = 0; h < GROUPS; h++) {
        l[h] = 0.f;
        acc[h][0] = acc[h][1] = acc[h][2] = acc[h][3] = 0.f;
    }

    // byte-base pointers; position stride = NKV*HD*4 = 2048 B
    const char* kB = (const char*)k_cache + ((size_t)b * LCACHE * NKV + kv) * HD * 4;
    const char* vB = (const char*)v_cache + ((size_t)b * LCACHE * NKV + kv) * HD * 4;
    const int pt0 = split * SPLIT_LEN;

    // warp w, tile t covers positions pt0 + t*TILE + 2w + {0,1};
    // lane copies its own 16B segment of each row
#define ISSUE(t) do {                                                         \
        const int _s = (t) & (NSTG - 1);                                      \
        const size_t _o = (size_t)(pt0 + (t) * TILE + 2 * warp) * 2048        \
                          + (size_t)lane * 16;                                \
        cp16(&kring[warp][_s][0][lane * 4], kB + _o);                         \
        cp16(&kring[warp][_s][1][lane * 4], kB + _o + 2048);                  \
        cp16(&vring[warp][_s][0][lane * 4], vB + _o);                         \
        cp16(&vring[warp][_s][1][lane * 4], vB + _o + 2048);                  \
    } while (0)

    // prologue: 3 tiles in flight
#pragma unroll
    for (int t = 0; t < NSTG - 1; t++) { ISSUE(t); cp_commit(); }

    const bool hi16 = (lane & 16) != 0;
    const bool hi8  = (lane & 8) != 0;
    const bool hi4  = (lane & 4) != 0;

    for (int t = 0; t < NT; t++) {
        cp_wait2();   // own groups: tile t complete (groups are per-thread)

        const int s = t & (NSTG - 1);
        float4 k0 = ((const float4*)kring[warp][s][0])[lane];
        float4 k1 = ((const float4*)kring[warp][s][1])[lane];
        float4 v0 = ((const float4*)vring[warp][s][0])[lane];
        float4 v1 = ((const float4*)vring[warp][s][1])[lane];

        if (t + NSTG - 1 < NT) ISSUE(t + NSTG - 1);   // stage (t-1)%4: consumed last iter
        cp_commit();                                   // unconditional: keeps group count aligned

        // 8 partial dots: value (p0,h) ends at lane 4h, (p1,h) at lane 16+4h
        float a[8];
#pragma unroll
        for (int h = 0; h < GROUPS; h++) {
            a[h]     = qf[h][0] * k0.x + qf[h][1] * k0.y + qf[h][2] * k0.z + qf[h][3] * k0.w;
            a[4 + h] = qf[h][0] * k1.x + qf[h][1] * k1.y + qf[h][2] * k1.z + qf[h][3] * k1.w;
        }

        // pack-exchange reduction: 7 SHFL total
        float b4[4];
#pragma unroll
        for (int u = 0; u < 4; u++) {
            float send = hi16 ? a[u] : a[u + 4];
            float rcv  = __shfl_xor_sync(FULLM, send, 16);
            b4[u] = (hi16 ? a[u + 4] : a[u]) + rcv;
        }
        float c2[2];
#pragma unroll
        for (int u = 0; u < 2; u++) {
            float send = hi8 ? b4[u] : b4[u + 2];
            float rcv  = __shfl_xor_sync(FULLM, send, 8);
            c2[u] = (hi8 ? b4[u + 2] : b4[u]) + rcv;
        }
        {
            float send = hi4 ? c2[0] : c2[1];
            float rcv  = __shfl_xor_sync(FULLM, send, 4);
            c2[0] = (hi4 ? c2[1] : c2[0]) + rcv;
        }
        float d1 = c2[0];
        d1 += __shfl_xor_sync(FULLM, d1, 2);
        d1 += __shfl_xor_sync(FULLM, d1, 1);

        float pw = ex2(d1 - MBIAS);

#pragma unroll
        for (int h = 0; h < GROUPS; h++) {
            float p0w = __shfl_sync(FULLM, pw, 4 * h);
            float p1w = __shfl_sync(FULLM, pw, 16 + 4 * h);
            l[h] += p0w + p1w;
            acc[h][0] = fmaf(p0w, v0.x, fmaf(p1w, v1.x, acc[h][0]));
            acc[h][1] = fmaf(p0w, v0.y, fmaf(p1w, v1.y, acc[h][1]));
            acc[h][2] = fmaf(p0w, v0.z, fmaf(p1w, v1.z, acc[h][2]));
            acc[h][3] = fmaf(p0w, v0.w, fmaf(p1w, v1.w, acc[h][3]));
        }
    }

    // new token (pos LCACHE): warp 3 of the last split, warp-local tail
    if (split == NSPLIT - 1 && warp == AW - 1) {
        float4 k0 = ((const float4*)&g_kn[b][kv][0])[lane];
        float4 v0 = ((const float4*)&g_vn[b][kv][0])[lane];

        float a[8];
#pragma unroll
        for (int h = 0; h < GROUPS; h++) {
            a[h]     = qf[h][0] * k0.x + qf[h][1] * k0.y + qf[h][2] * k0.z + qf[h][3] * k0.w;
            a[4 + h] = a[h];   // dummy p1, weight forced to 0 below
        }
        float b4[4];
#pragma unroll
        for (int u = 0; u < 4; u++) {
            float send = hi16 ? a[u] : a[u + 4];
            float rcv  = __shfl_xor_sync(FULLM, send, 16);
            b4[u] = (hi16 ? a[u + 4] : a[u]) + rcv;
        }
        float c2[2];
#pragma unroll
        for (int u = 0; u < 2; u++) {
            float send = hi8 ? b4[u] : b4[u + 2];
            float rcv  = __shfl_xor_sync(FULLM, send, 8);
            c2[u] = (hi8 ? b4[u + 2] : b4[u]) + rcv;
        }
        {
            float send = hi4 ? c2[0] : c2[1];
            float rcv  = __shfl_xor_sync(FULLM, send, 4);
            c2[0] = (hi4 ? c2[1] : c2[0]) + rcv;
        }
        float d1 = c2[0];
        d1 += __shfl_xor_sync(FULLM, d1, 2);
        d1 += __shfl_xor_sync(FULLM, d1, 1);

        if (hi16) d1 = -CUDART_INF_F;   // p1 invalid -> weight 0
        float pw = ex2(d1 - MBIAS);

#pragma unroll
        for (int h = 0; h < GROUPS; h++) {
            float p0w = __shfl_sync(FULLM, pw, 4 * h);
            l[h] += p0w;
            acc[h][0] = fmaf(p0w, v0.x, acc[h][0]);
            acc[h][1] = fmaf(p0w, v0.y, acc[h][1]);
            acc[h][2] = fmaf(p0w, v0.z, acc[h][2]);
            acc[h][3] = fmaf(p0w, v0.w, acc[h][3]);
        }
    }

    // drain own in-flight copies before the ring memory is reused as scratch
    cp_wait0();
    __syncthreads();

    // reduce across warps; reuse kring storage for the per-warp accumulators
    float* sacc = &kring[0][0][0][0];   // [AW][GROUPS][HD] = 8 KB
#pragma unroll
    for (int h = 0; h < GROUPS; h++) {
        float* dst = sacc + (warp * GROUPS + h) * HD + lane * 4;
        dst[0] = acc[h][0]; dst[1] = acc[h][1]; dst[2] = acc[h][2]; dst[3] = acc[h][3];
        if (lane == 0) s_l[warp][h] = l[h];
    }
    __syncthreads();

    for (int i = tid; i < GROUPS * HD; i += 128) {
        const int h = i >> 7, d = i & 127;
        float num = 0.f;
#pragma unroll
        for (int w = 0; w < AW; w++) num += sacc[(w * GROUPS + h) * HD + d];
        g_pacc[pair][split][h][d] = num;
    }
    if (tid < GROUPS) {
        float tl = 0.f;
#pragma unroll
        for (int w = 0; w < AW; w++) tl += s_l[w][tid];
        g_pl[pair][split][tid] = tl;
    }
}

// ---------------- 4) combine split partials -> attn_out --------------------
__global__ void combine_k() {
    const int idx  = blockIdx.x;
    const int pair = idx >> 2;
    const int g    = idx & 3;
    const int tid  = threadIdx.x;

    __shared__ float s_gl;
    if (tid < 32) {
        float pl = (tid < NSPLIT) ? g_pl[pair][tid][g] : 0.f;
        float gl = pl;
#pragma unroll
        for (int o = 16; o; o >>= 1) gl += __shfl_xor_sync(FULLM, gl, o);
        if (tid == 0) s_gl = gl;
    }
    __syncthreads();

    float num = 0.f;
#pragma unroll
    for (int s = 0; s < NSPLIT; s++) num += g_pacc[pair][s][g][tid];

    const int b = pair >> 2, kv = pair & 3;
    g_attn[b][(kv * GROUPS + g) * HD + tid] = num / s_gl;
}

// ---------------- 5) O projection (256 k per CTA, two smem passes) ---------
__global__ void o_gemm_k(const float* __restrict__ w) {
    const int nblk = blockIdx.x;   // 0..15
    const int ks   = blockIdx.y;   // 0..7
    const int tid  = threadIdx.x;

    __shared__ float as_[BATCH][128];
    const int n = nblk * 128 + tid;
    float acc[BATCH];
#pragma unroll
    for (int b = 0; b < BATCH; b++) acc[b] = 0.f;

#pragma unroll
    for (int c = 0; c < 2; c++) {
        const int k0 = ks * 256 + c * 128;
        __syncthreads();
        for (int i = tid; i < BATCH * 128; i += 128) {
            int b = i >> 7, kk = i & 127;
            as_[b][kk] = g_attn[b][k0 + kk];
        }
        __syncthreads();

        const float* wp = w + (size_t)k0 * HID + n;
#pragma unroll 2
        for (int kk4 = 0; kk4 < 32; kk4++) {
            float w0 = __ldg(wp + (size_t)(kk4 * 4 + 0) * HID);
            float w1 = __ldg(wp + (size_t)(kk4 * 4 + 1) * HID);
            float w2 = __ldg(wp + (size_t)(kk4 * 4 + 2) * HID);
            float w3 = __ldg(wp + (size_t)(kk4 * 4 + 3) * HID);
#pragma unroll
            for (int b = 0; b < BATCH; b++) {
                float4 h4 = *(const float4*)&as_[b][kk4 * 4];
                acc[b] = fmaf(h4.x, w0, fmaf(h4.y, w1, fmaf(h4.z, w2, fmaf(h4.w, w3, acc[b]))));
            }
        }
    }
#pragma unroll
    for (int b = 0; b < BATCH; b++) g_opart[ks][b][n] = acc[b];
}

// ---------------- 6) sum O partials into d_out -----------------------------
__global__ void ocomb_k(float* __restrict__ out) {
    const int i = blockIdx.x * 256 + threadIdx.x;
    const float* p = &g_opart[0][0][0];
    float v = 0.f;
#pragma unroll
    for (int s = 0; s < KSPLIT; s++) v += p[(size_t)s * BATCH * HID + i];
    out[i] = v;
}

// ---------------- launch ----------------------------------------------------
extern "C" void kernel_launch(void* const* d_in, const int* in_sizes, int n_in,
                              void* d_out, int out_size) {
    const float* hidden  = (const float*)d_in[0];
    const float* k_cache = (const float*)d_in[1];
    const float* v_cache = (const float*)d_in[2];
    const float* w_qkv   = (const float*)d_in[3];
    const float* b_qkv   = (const float*)d_in[4];
    const float* w_o     = (const float*)d_in[5];
    const float* q_gamma = (const float*)d_in[6];
    const float* k_gamma = (const float*)d_in[7];
    float* out = (float*)d_out;

    qkv_gemm_k<<<dim3(QKVW / 128, KSPLIT), 128>>>(hidden, w_qkv);
    rmsnorm_k<<<dim3(QKVW / 128, BATCH), 128>>>(b_qkv, q_gamma, k_gamma);
    attn_k<<<dim3(NSPLIT, BATCH * NKV), 128>>>(k_cache, v_cache);
    combine_k<<<BATCH * NKV * GROUPS, 128>>>();
    o_gemm_k<<<dim3(HID / 128, KSPLIT), 128>>>(w_o);
    ocomb_k<<<(BATCH * HID) / 256, 256>>>(out);
}

// round 17
// speedup vs baseline: 1.2229x; 1.2229x over previous
#include <cuda_runtime.h>
#include <math_constants.h>

#define BATCH   32
#define LCACHE  8192
#define NKV     4
#define NH      16
#define HD      128
#define HID     2048
#define QKVW    3072          // 2048 q + 512 k + 512 v
#define GROUPS  4             // NH / NKV
#define NSPLIT  32
#define SPLIT_LEN 256         // LCACHE / NSPLIT
#define KSPLIT  16
#define AW      4             // warps per attn CTA
#define TILE    8             // positions per tile (2 per warp)
#define NSTG    4             // per-warp cp.async ring stages
#define NT      (SPLIT_LEN / TILE)   // 32 tiles per CTA

// scale * log2(e) : (1/sqrt(128)) * 1.4426950408889634
#define SCLOG2E (1.4426950408889634f * 0.08838834764831845f)
// fixed softmax bias in log2 space (validated R5/R7/R10-R16): pw = 2^(s-20)
#define MBIAS   20.0f
#define FULLM   0xffffffffu

__device__ __forceinline__ float ex2(float x) {
    float y; asm("ex2.approx.ftz.f32 %0, %1;" : "=f"(y) : "f"(x)); return y;
}
__device__ __forceinline__ void cp16(void* smem, const void* gmem) {
    unsigned sa = (unsigned)__cvta_generic_to_shared(smem);
    asm volatile("cp.async.cg.shared.global [%0], [%1], 16;" :: "r"(sa), "l"(gmem));
}
__device__ __forceinline__ void cp_commit() {
    asm volatile("cp.async.commit_group;");
}
__device__ __forceinline__ void cp_wait2() {
    asm volatile("cp.async.wait_group 2;");
}
__device__ __forceinline__ void cp_wait0() {
    asm volatile("cp.async.wait_group 0;");
}

// ---------------- scratch (device globals) ---------------------------------
__device__ float g_qkv_part[KSPLIT][BATCH][QKVW];
__device__ float g_qn[BATCH][NH][HD];
__device__ float g_kn[BATCH][NKV][HD];
__device__ float g_vn[BATCH][NKV][HD];
__device__ float g_pacc[BATCH * NKV][NSPLIT][GROUPS][HD];
__device__ float g_pl[BATCH * NKV][NSPLIT][GROUPS];
__device__ float g_attn[BATCH][HID];
__device__ float g_opart[KSPLIT][BATCH][HID];

// ---------------- 1) QKV GEMM ----------------------------------------------
__global__ void qkv_gemm_k(const float* __restrict__ hidden,
                           const float* __restrict__ w) {
    const int nblk = blockIdx.x;
    const int ks   = blockIdx.y;
    const int tid  = threadIdx.x;

    __shared__ float hs[BATCH][128];
    for (int i = tid; i < BATCH * 128; i += 128) {
        int b = i >> 7, kk = i & 127;
        hs[b][kk] = hidden[b * HID + ks * 128 + kk];
    }
    __syncthreads();

    const int n = nblk * 128 + tid;
    float acc[BATCH];
#pragma unroll
    for (int b = 0; b < BATCH; b++) acc[b] = 0.f;

    const float* wp = w + (size_t)(ks * 128) * QKVW + n;
#pragma unroll 2
    for (int kk4 = 0; kk4 < 32; kk4++) {
        float w0 = __ldg(wp + (size_t)(kk4 * 4 + 0) * QKVW);
        float w1 = __ldg(wp + (size_t)(kk4 * 4 + 1) * QKVW);
        float w2 = __ldg(wp + (size_t)(kk4 * 4 + 2) * QKVW);
        float w3 = __ldg(wp + (size_t)(kk4 * 4 + 3) * QKVW);
#pragma unroll
        for (int b = 0; b < BATCH; b++) {
            float4 h4 = *(const float4*)&hs[b][kk4 * 4];
            acc[b] = fmaf(h4.x, w0, fmaf(h4.y, w1, fmaf(h4.z, w2, fmaf(h4.w, w3, acc[b]))));
        }
    }
#pragma unroll
    for (int b = 0; b < BATCH; b++) g_qkv_part[ks][b][n] = acc[b];
}

// ---------------- 2) sum partials + bias + per-head RMSNorm ----------------
__global__ void rmsnorm_k(const float* __restrict__ b_qkv,
                          const float* __restrict__ q_gamma,
                          const float* __restrict__ k_gamma) {
    const int seg = blockIdx.x;
    const int b   = blockIdx.y;
    const int tid = threadIdx.x;
    const int col = seg * 128 + tid;

    float v = b_qkv[col];
#pragma unroll
    for (int s = 0; s < KSPLIT; s++) v += g_qkv_part[s][b][col];

    if (seg < 20) {
        float ss = v * v;
#pragma unroll
        for (int o = 16; o; o >>= 1) ss += __shfl_xor_sync(FULLM, ss, o);
        __shared__ float wsum[4];
        if ((tid & 31) == 0) wsum[tid >> 5] = ss;
        __syncthreads();
        float tot = wsum[0] + wsum[1] + wsum[2] + wsum[3];
        float r = rsqrtf(tot * (1.f / 128.f) + 1e-6f);
        if (seg < 16) g_qn[b][seg][tid]      = v * r * q_gamma[tid];
        else          g_kn[b][seg - 16][tid] = v * r * k_gamma[tid];
    } else {
        g_vn[b][seg - 20][tid] = v;
    }
}

// ---------------- 3) flash-decode: R12-exact body, warp-private rings ------
__global__ void __launch_bounds__(128, 6)
attn_k(const float* __restrict__ k_cache, const float* __restrict__ v_cache) {
    const int split = blockIdx.x;
    const int pair  = blockIdx.y;
    const int b     = pair >> 2;
    const int kv    = pair & 3;
    const int tid   = threadIdx.x;
    const int warp  = tid >> 5;
    const int lane  = tid & 31;

    // per-warp private rings: each lane reads back exactly the 16B segment
    // it copied -> per-thread wait_group suffices, no CTA barrier.
    __shared__ __align__(16) float kring[AW][NSTG][2][HD];  // 16 KB
    __shared__ __align__(16) float vring[AW][NSTG][2][HD];  // 16 KB
    __shared__ float qs[GROUPS][HD];                        // 2 KB
    __shared__ float s_l[AW][GROUPS];

    // q scaled by scale*log2e, then kept in registers
    for (int i = tid; i < GROUPS * HD; i += 128)
        qs[i >> 7][i & 127] = g_qn[b][kv * GROUPS + (i >> 7)][i & 127] * SCLOG2E;
    __syncthreads();

    float qf[GROUPS][4];
#pragma unroll
    for (int h = 0; h < GROUPS; h++) {
        float4 q4 = *(const float4*)&qs[h][lane * 4];
        qf[h][0] = q4.x; qf[h][1] = q4.y; qf[h][2] = q4.z; qf[h][3] = q4.w;
    }

    float l[GROUPS], acc[GROUPS][4];
#pragma unroll
    for (int h = 0; h < GROUPS; h++) {
        l[h] = 0.f;
        acc[h][0] = acc[h][1] = acc[h][2] = acc[h][3] = 0.f;
    }

    // byte-base pointers; position stride = NKV*HD*4 = 2048 B
    const char* kB = (const char*)k_cache + ((size_t)b * LCACHE * NKV + kv) * HD * 4;
    const char* vB = (const char*)v_cache + ((size_t)b * LCACHE * NKV + kv) * HD * 4;
    const int pt0 = split * SPLIT_LEN;

    // warp w, tile t covers positions pt0 + t*TILE + 2w + {0,1};
    // lane copies its own 16B segment of each row
#define ISSUE(t) do {                                                         \
        const int _s = (t) & (NSTG - 1);                                      \
        const size_t _o = (size_t)(pt0 + (t) * TILE + 2 * warp) * 2048        \
                          + (size_t)lane * 16;                                \
        cp16(&kring[warp][_s][0][lane * 4], kB + _o);                         \
        cp16(&kring[warp][_s][1][lane * 4], kB + _o + 2048);                  \
        cp16(&vring[warp][_s][0][lane * 4], vB + _o);                         \
        cp16(&vring[warp][_s][1][lane * 4], vB + _o + 2048);                  \
    } while (0)

    // prologue: 3 tiles in flight
#pragma unroll
    for (int t = 0; t < NSTG - 1; t++) { ISSUE(t); cp_commit(); }

    const bool hi16 = (lane & 16) != 0;
    const bool hi8  = (lane & 8) != 0;
    const bool hi4  = (lane & 4) != 0;

    for (int t = 0; t < NT; t++) {
        cp_wait2();   // own groups: tile t complete (groups are per-thread)

        const int s = t & (NSTG - 1);
        float4 k0 = ((const float4*)kring[warp][s][0])[lane];
        float4 k1 = ((const float4*)kring[warp][s][1])[lane];
        float4 v0 = ((const float4*)vring[warp][s][0])[lane];
        float4 v1 = ((const float4*)vring[warp][s][1])[lane];

        if (t + NSTG - 1 < NT) ISSUE(t + NSTG - 1);   // stage (t-1)%4: consumed last iter
        cp_commit();                                   // unconditional: keeps group count aligned

        // 8 partial dots: value (p0,h) ends at lane 4h, (p1,h) at lane 16+4h
        float a[8];
#pragma unroll
        for (int h = 0; h < GROUPS; h++) {
            a[h]     = qf[h][0] * k0.x + qf[h][1] * k0.y + qf[h][2] * k0.z + qf[h][3] * k0.w;
            a[4 + h] = qf[h][0] * k1.x + qf[h][1] * k1.y + qf[h][2] * k1.z + qf[h][3] * k1.w;
        }

        // pack-exchange reduction: 7 SHFL total
        float b4[4];
#pragma unroll
        for (int u = 0; u < 4; u++) {
            float send = hi16 ? a[u] : a[u + 4];
            float rcv  = __shfl_xor_sync(FULLM, send, 16);
            b4[u] = (hi16 ? a[u + 4] : a[u]) + rcv;
        }
        float c2[2];
#pragma unroll
        for (int u = 0; u < 2; u++) {
            float send = hi8 ? b4[u] : b4[u + 2];
            float rcv  = __shfl_xor_sync(FULLM, send, 8);
            c2[u] = (hi8 ? b4[u + 2] : b4[u]) + rcv;
        }
        {
            float send = hi4 ? c2[0] : c2[1];
            float rcv  = __shfl_xor_sync(FULLM, send, 4);
            c2[0] = (hi4 ? c2[1] : c2[0]) + rcv;
        }
        float d1 = c2[0];
        d1 += __shfl_xor_sync(FULLM, d1, 2);
        d1 += __shfl_xor_sync(FULLM, d1, 1);

        float pw = ex2(d1 - MBIAS);

#pragma unroll
        for (int h = 0; h < GROUPS; h++) {
            float p0w = __shfl_sync(FULLM, pw, 4 * h);
            float p1w = __shfl_sync(FULLM, pw, 16 + 4 * h);
            l[h] += p0w + p1w;
            acc[h][0] = fmaf(p0w, v0.x, fmaf(p1w, v1.x, acc[h][0]));
            acc[h][1] = fmaf(p0w, v0.y, fmaf(p1w, v1.y, acc[h][1]));
            acc[h][2] = fmaf(p0w, v0.z, fmaf(p1w, v1.z, acc[h][2]));
            acc[h][3] = fmaf(p0w, v0.w, fmaf(p1w, v1.w, acc[h][3]));
        }
    }

    // new token (pos LCACHE): warp 3 of the last split, warp-local tail
    if (split == NSPLIT - 1 && warp == AW - 1) {
        float4 k0 = ((const float4*)&g_kn[b][kv][0])[lane];
        float4 v0 = ((const float4*)&g_vn[b][kv][0])[lane];

        float a[8];
#pragma unroll
        for (int h = 0; h < GROUPS; h++) {
            a[h]     = qf[h][0] * k0.x + qf[h][1] * k0.y + qf[h][2] * k0.z + qf[h][3] * k0.w;
            a[4 + h] = a[h];   // dummy p1, weight forced to 0 below
        }
        float b4[4];
#pragma unroll
        for (int u = 0; u < 4; u++) {
            float send = hi16 ? a[u] : a[u + 4];
            float rcv  = __shfl_xor_sync(FULLM, send, 16);
            b4[u] = (hi16 ? a[u + 4] : a[u]) + rcv;
        }
        float c2[2];
#pragma unroll
        for (int u = 0; u < 2; u++) {
            float send = hi8 ? b4[u] : b4[u + 2];
            float rcv  = __shfl_xor_sync(FULLM, send, 8);
            c2[u] = (hi8 ? b4[u + 2] : b4[u]) + rcv;
        }
        {
            float send = hi4 ? c2[0] : c2[1];
            float rcv  = __shfl_xor_sync(FULLM, send, 4);
            c2[0] = (hi4 ? c2[1] : c2[0]) + rcv;
        }
        float d1 = c2[0];
        d1 += __shfl_xor_sync(FULLM, d1, 2);
        d1 += __shfl_xor_sync(FULLM, d1, 1);

        if (hi16) d1 = -CUDART_INF_F;   // p1 invalid -> weight 0
        float pw = ex2(d1 - MBIAS);

#pragma unroll
        for (int h = 0; h < GROUPS; h++) {
            float p0w = __shfl_sync(FULLM, pw, 4 * h);
            l[h] += p0w;
            acc[h][0] = fmaf(p0w, v0.x, acc[h][0]);
            acc[h][1] = fmaf(p0w, v0.y, acc[h][1]);
            acc[h][2] = fmaf(p0w, v0.z, acc[h][2]);
            acc[h][3] = fmaf(p0w, v0.w, acc[h][3]);
        }
    }

    // drain own in-flight copies before the ring memory is reused as scratch
    cp_wait0();
    __syncthreads();

    // reduce across warps; reuse kring storage for the per-warp accumulators
    float* sacc = &kring[0][0][0][0];   // [AW][GROUPS][HD] = 8 KB
#pragma unroll
    for (int h = 0; h < GROUPS; h++) {
        float* dst = sacc + (warp * GROUPS + h) * HD + lane * 4;
        dst[0] = acc[h][0]; dst[1] = acc[h][1]; dst[2] = acc[h][2]; dst[3] = acc[h][3];
        if (lane == 0) s_l[warp][h] = l[h];
    }
    __syncthreads();

    for (int i = tid; i < GROUPS * HD; i += 128) {
        const int h = i >> 7, d = i & 127;
        float num = 0.f;
#pragma unroll
        for (int w = 0; w < AW; w++) num += sacc[(w * GROUPS + h) * HD + d];
        g_pacc[pair][split][h][d] = num;
    }
    if (tid < GROUPS) {
        float tl = 0.f;
#pragma unroll
        for (int w = 0; w < AW; w++) tl += s_l[w][tid];
        g_pl[pair][split][tid] = tl;
    }
}

// ---------------- 4) combine split partials -> attn_out --------------------
__global__ void combine_k() {
    const int idx  = blockIdx.x;
    const int pair = idx >> 2;
    const int g    = idx & 3;
    const int tid  = threadIdx.x;

    __shared__ float s_gl;
    if (tid < 32) {
        float pl = (tid < NSPLIT) ? g_pl[pair][tid][g] : 0.f;
        float gl = pl;
#pragma unroll
        for (int o = 16; o; o >>= 1) gl += __shfl_xor_sync(FULLM, gl, o);
        if (tid == 0) s_gl = gl;
    }
    __syncthreads();

    float num = 0.f;
#pragma unroll
    for (int s = 0; s < NSPLIT; s++) num += g_pacc[pair][s][g][tid];

    const int b = pair >> 2, kv = pair & 3;
    g_attn[b][(kv * GROUPS + g) * HD + tid] = num / s_gl;
}

// ---------------- 5) O projection ------------------------------------------
__global__ void o_gemm_k(const float* __restrict__ w) {
    const int nblk = blockIdx.x;
    const int ks   = blockIdx.y;
    const int tid  = threadIdx.x;

    __shared__ float as_[BATCH][128];
    for (int i = tid; i < BATCH * 128; i += 128) {
        int b = i >> 7, kk = i & 127;
        as_[b][kk] = g_attn[b][ks * 128 + kk];
    }
    __syncthreads();

    const int n = nblk * 128 + tid;
    float acc[BATCH];
#pragma unroll
    for (int b = 0; b < BATCH; b++) acc[b] = 0.f;

    const float* wp = w + (size_t)(ks * 128) * HID + n;
#pragma unroll 2
    for (int kk4 = 0; kk4 < 32; kk4++) {
        float w0 = __ldg(wp + (size_t)(kk4 * 4 + 0) * HID);
        float w1 = __ldg(wp + (size_t)(kk4 * 4 + 1) * HID);
        float w2 = __ldg(wp + (size_t)(kk4 * 4 + 2) * HID);
        float w3 = __ldg(wp + (size_t)(kk4 * 4 + 3) * HID);
#pragma unroll
        for (int b = 0; b < BATCH; b++) {
            float4 h4 = *(const float4*)&as_[b][kk4 * 4];
            acc[b] = fmaf(h4.x, w0, fmaf(h4.y, w1, fmaf(h4.z, w2, fmaf(h4.w, w3, acc[b]))));
        }
    }
#pragma unroll
    for (int b = 0; b < BATCH; b++) g_opart[ks][b][n] = acc[b];
}

// ---------------- 6) sum O partials into d_out (float4-vectorized) ---------
__global__ void ocomb_k(float* __restrict__ out) {
    const int i4 = blockIdx.x * 256 + threadIdx.x;   // < 16384 float4s
    const float4* p = (const float4*)&g_opart[0][0][0];
    float4 v = make_float4(0.f, 0.f, 0.f, 0.f);
#pragma unroll
    for (int s = 0; s < KSPLIT; s++) {
        float4 t = p[(size_t)s * (BATCH * HID / 4) + i4];
        v.x += t.x; v.y += t.y; v.z += t.z; v.w += t.w;
    }
    ((float4*)out)[i4] = v;
}

// ---------------- launch ----------------------------------------------------
extern "C" void kernel_launch(void* const* d_in, const int* in_sizes, int n_in,
                              void* d_out, int out_size) {
    const float* hidden  = (const float*)d_in[0];
    const float* k_cache = (const float*)d_in[1];
    const float* v_cache = (const float*)d_in[2];
    const float* w_qkv   = (const float*)d_in[3];
    const float* b_qkv   = (const float*)d_in[4];
    const float* w_o     = (const float*)d_in[5];
    const float* q_gamma = (const float*)d_in[6];
    const float* k_gamma = (const float*)d_in[7];
    float* out = (float*)d_out;

    qkv_gemm_k<<<dim3(QKVW / 128, KSPLIT), 128>>>(hidden, w_qkv);
    rmsnorm_k<<<dim3(QKVW / 128, BATCH), 128>>>(b_qkv, q_gamma, k_gamma);
    attn_k<<<dim3(NSPLIT, BATCH * NKV), 128>>>(k_cache, v_cache);
    combine_k<<<BATCH * NKV * GROUPS, 128>>>();
    o_gemm_k<<<dim3(HID / 128, KSPLIT), 128>>>(w_o);
    ocomb_k<<<(BATCH * HID / 4) / 256, 256>>>(out);
}